// round 1
// baseline (speedup 1.0000x reference)
#include <cuda_runtime.h>
#include <cstddef>

// Problem constants (fixed-shape problem):
//   N=512 atoms, D=128 descriptor dim, H=128 hidden, S=4 species
//   coord_grads: [N, 3N=1536, D]   strain_grads: [N, 6, D]
//   out: [1 + 1536 + 6] = [E_sum, forces(1536), stress(6)]
#define NATOMS 512
#define DDIM   128
#define KDIM   1536   // 3*N
#define NSTR   6
#define KTOT   (KDIM + NSTR + 1)   // 1543 reduction slots (forces, stress, energy)

// Scratch: per-(slot, atom) partials. 1543*512*4B = 3.16 MB. Deterministic reduce.
__device__ __align__(16) float g_partial[KTOT * NATOMS];

// ---------------------------------------------------------------------------
// Fused kernel: one block per atom.
//   Phase 1 (threads 0..127): species MLP forward + backward -> G[n,:] in smem,
//                             per-atom energy E_n.
//   Phase 2 (all 16 warps):   stream CG[n,:,:] (786 KB) coalesced float4,
//                             warp-per-k dot with G; plus 6 stress rows.
// ---------------------------------------------------------------------------
__global__ __launch_bounds__(512, 2) void nnp_fused_kernel(
    const float* __restrict__ desc,   // [N, D]
    const float* __restrict__ CG,     // [N, KDIM, D]
    const float* __restrict__ SG,     // [N, 6, D]
    const float* __restrict__ W0,     // [S, H, D]
    const float* __restrict__ b0,     // [S, H]
    const float* __restrict__ W1,     // [S, H, H]
    const float* __restrict__ b1,     // [S, H]
    const float* __restrict__ W2,     // [S, 1, H]
    const float* __restrict__ b2,     // [S, 1]
    const int*   __restrict__ species)
{
    const int n    = blockIdx.x;
    const int tid  = threadIdx.x;
    const int wid  = tid >> 5;
    const int lane = tid & 31;

    __shared__ __align__(16) float sdesc[DDIM];
    __shared__ __align__(16) float sh0[DDIM];   // tanh activations layer 0
    __shared__ __align__(16) float sa0[DDIM];   // 1 - h0^2
    __shared__ __align__(16) float sh1[DDIM];   // tanh activations layer 1
    __shared__ __align__(16) float sa1[DDIM];   // 1 - h1^2  (later reused as d0)
    __shared__ __align__(16) float sd1[DDIM];   // d1 = w2 * (1 - h1^2)
    __shared__ __align__(16) float sred[DDIM];  // energy partials
    __shared__ __align__(16) float sG[DDIM];    // dE/ddesc for this atom

    const int sp = species[n];

    if (tid < DDIM) sdesc[tid] = desc[n * DDIM + tid];
    __syncthreads();

    // ---- layer 0: h0 = tanh(W0 @ desc + b0), row per thread ----
    if (tid < DDIM) {
        const float* w = W0 + (size_t)sp * DDIM * DDIM + (size_t)tid * DDIM;
        float a0 = b0[sp * DDIM + tid], a1 = 0.f, a2 = 0.f, a3 = 0.f;
        #pragma unroll
        for (int d = 0; d < DDIM; d += 4) {
            a0 += w[d + 0] * sdesc[d + 0];
            a1 += w[d + 1] * sdesc[d + 1];
            a2 += w[d + 2] * sdesc[d + 2];
            a3 += w[d + 3] * sdesc[d + 3];
        }
        float h = tanhf(a0 + a1 + a2 + a3);
        sh0[tid] = h;
        sa0[tid] = 1.f - h * h;
    }
    __syncthreads();

    // ---- layer 1: h1 = tanh(W1 @ h0 + b1) ----
    if (tid < DDIM) {
        const float* w = W1 + (size_t)sp * DDIM * DDIM + (size_t)tid * DDIM;
        float a0 = b1[sp * DDIM + tid], a1 = 0.f, a2 = 0.f, a3 = 0.f;
        #pragma unroll
        for (int d = 0; d < DDIM; d += 4) {
            a0 += w[d + 0] * sh0[d + 0];
            a1 += w[d + 1] * sh0[d + 1];
            a2 += w[d + 2] * sh0[d + 2];
            a3 += w[d + 3] * sh0[d + 3];
        }
        float h = tanhf(a0 + a1 + a2 + a3);
        sh1[tid] = h;
        sa1[tid] = 1.f - h * h;
    }
    __syncthreads();

    // ---- output layer partials + d1 (backprop through layer 2) ----
    if (tid < DDIM) {
        float w2v = W2[sp * DDIM + tid];
        sred[tid] = w2v * sh1[tid];
        sd1[tid]  = w2v * sa1[tid];
    }
    __syncthreads();

    if (tid == 0) {
        float e = b2[sp];
        #pragma unroll 8
        for (int i = 0; i < DDIM; i++) e += sred[i];
        g_partial[(KDIM + NSTR) * NATOMS + n] = e;   // energy slot
    }
    __syncthreads();

    // ---- g1 = W1^T @ d1 ; d0 = g1 * (1 - h0^2)   (coalesced column reads) ----
    if (tid < DDIM) {
        const float* w = W1 + (size_t)sp * DDIM * DDIM + tid;
        float a0 = 0.f, a1 = 0.f;
        #pragma unroll 8
        for (int j = 0; j < DDIM; j += 2) {
            a0 += w[(size_t)(j + 0) * DDIM] * sd1[j + 0];
            a1 += w[(size_t)(j + 1) * DDIM] * sd1[j + 1];
        }
        sa1[tid] = (a0 + a1) * sa0[tid];   // sa1 now holds d0
    }
    __syncthreads();

    // ---- G = W0^T @ d0 ----
    if (tid < DDIM) {
        const float* w = W0 + (size_t)sp * DDIM * DDIM + tid;
        float a0 = 0.f, a1 = 0.f;
        #pragma unroll 8
        for (int j = 0; j < DDIM; j += 2) {
            a0 += w[(size_t)(j + 0) * DDIM] * sa1[j + 0];
            a1 += w[(size_t)(j + 1) * DDIM] * sa1[j + 1];
        }
        sG[tid] = a0 + a1;
    }
    __syncthreads();

    // ---- Phase 2: stream coord_grads[n,:,:] — warp per k-row ----
    const float4* sG4  = reinterpret_cast<const float4*>(sG);
    const float4  gv   = sG4[lane];
    const size_t  base = (size_t)n * KDIM * DDIM;

    for (int k = wid; k < KDIM; k += 16) {
        const float4* row = reinterpret_cast<const float4*>(CG + base + (size_t)k * DDIM);
        float4 v = row[lane];
        float s = v.x * gv.x + v.y * gv.y + v.z * gv.z + v.w * gv.w;
        #pragma unroll
        for (int off = 16; off > 0; off >>= 1)
            s += __shfl_xor_sync(0xFFFFFFFFu, s, off);
        if (lane == 0) g_partial[(size_t)k * NATOMS + n] = s;
    }

    // ---- stress rows: 6 rows of 128 ----
    if (wid < NSTR) {
        const float4* row = reinterpret_cast<const float4*>(SG + ((size_t)n * NSTR + wid) * DDIM);
        float4 v = row[lane];
        float s = v.x * gv.x + v.y * gv.y + v.z * gv.z + v.w * gv.w;
        #pragma unroll
        for (int off = 16; off > 0; off >>= 1)
            s += __shfl_xor_sync(0xFFFFFFFFu, s, off);
        if (lane == 0) g_partial[(size_t)(KDIM + wid) * NATOMS + n] = s;
    }
}

// ---------------------------------------------------------------------------
// Reduce kernel: warp per output slot, sum 512 partials (fixed order), write out.
//   out[0] = sum(E); out[1..1536] = forces; out[1537..1542] = -stress/volume
// ---------------------------------------------------------------------------
__global__ void nnp_reduce_kernel(float* __restrict__ out,
                                  const float* __restrict__ volume)
{
    const int k    = blockIdx.x * 8 + (threadIdx.x >> 5);
    const int lane = threadIdx.x & 31;
    if (k >= KTOT) return;

    const float4* base = reinterpret_cast<const float4*>(g_partial + (size_t)k * NATOMS);
    float s = 0.f;
    #pragma unroll
    for (int i = 0; i < 4; i++) {           // 4 * 32 lanes * float4 = 512 floats
        float4 v = base[lane + i * 32];
        s += v.x + v.y + v.z + v.w;
    }
    #pragma unroll
    for (int off = 16; off > 0; off >>= 1)
        s += __shfl_xor_sync(0xFFFFFFFFu, s, off);

    if (lane == 0) {
        if (k < KDIM)            out[1 + k] = s;                       // forces
        else if (k < KDIM + NSTR) out[1 + KDIM + (k - KDIM)] = -s / volume[0]; // stress
        else                      out[0] = s;                          // energy
    }
}

extern "C" void kernel_launch(void* const* d_in, const int* in_sizes, int n_in,
                              void* d_out, int out_size)
{
    const float* desc    = (const float*)d_in[0];
    const float* CG      = (const float*)d_in[1];
    const float* SG      = (const float*)d_in[2];
    const float* W0      = (const float*)d_in[3];
    const float* b0      = (const float*)d_in[4];
    const float* W1      = (const float*)d_in[5];
    const float* b1      = (const float*)d_in[6];
    const float* W2      = (const float*)d_in[7];
    const float* b2      = (const float*)d_in[8];
    const float* volume  = (const float*)d_in[9];
    const int*   species = (const int*)  d_in[10];
    float* out = (float*)d_out;

    nnp_fused_kernel<<<NATOMS, 512>>>(desc, CG, SG, W0, b0, W1, b1, W2, b2, species);
    nnp_reduce_kernel<<<(KTOT + 7) / 8, 256>>>(out, volume);
}

// round 2
// speedup vs baseline: 1.0957x; 1.0957x over previous
#include <cuda_runtime.h>
#include <cstddef>

#define NATOMS 512
#define DDIM   128
#define KDIM   1536   // 3*N
#define NSTR   6
#define KTOT   (KDIM + NSTR + 1)   // forces, stress, energy slots

#define BLOCKS_PER_ATOM 6          // 6 * 256 rows = 1536
#define STREAM_THREADS  256

// Scratch: per-(slot, atom) partials (3.16 MB) + per-atom gradient G (256 KB).
__device__ __align__(16) float g_partial[KTOT * NATOMS];
__device__ __align__(16) float g_G[NATOMS * DDIM];

// ---------------------------------------------------------------------------
// Kernel 1: per-atom species MLP forward + backward.
//   -> g_G[n,:] (dE/ddesc), energy partial, 6 stress partials.
// ---------------------------------------------------------------------------
__global__ __launch_bounds__(128) void nnp_mlp_kernel(
    const float* __restrict__ desc,   // [N, D]
    const float* __restrict__ SG,     // [N, 6, D]
    const float* __restrict__ W0,     // [S, H, D]
    const float* __restrict__ b0,     // [S, H]
    const float* __restrict__ W1,     // [S, H, H]
    const float* __restrict__ b1,     // [S, H]
    const float* __restrict__ W2,     // [S, 1, H]
    const float* __restrict__ b2,     // [S, 1]
    const int*   __restrict__ species)
{
    const int n    = blockIdx.x;
    const int tid  = threadIdx.x;
    const int wid  = tid >> 5;
    const int lane = tid & 31;

    __shared__ __align__(16) float sdesc[DDIM];
    __shared__ __align__(16) float sh0[DDIM];
    __shared__ __align__(16) float sa0[DDIM];
    __shared__ __align__(16) float sd1[DDIM];
    __shared__ __align__(16) float sa1[DDIM];   // reused: (1-h1^2), then d0
    __shared__ __align__(16) float sred[DDIM];
    __shared__ __align__(16) float sG[DDIM];

    const int sp = species[n];
    sdesc[tid] = desc[n * DDIM + tid];
    __syncthreads();

    // layer 0
    {
        const float* w = W0 + (size_t)sp * DDIM * DDIM + (size_t)tid * DDIM;
        float a0 = b0[sp * DDIM + tid], a1 = 0.f, a2 = 0.f, a3 = 0.f;
        #pragma unroll
        for (int d = 0; d < DDIM; d += 4) {
            a0 += w[d + 0] * sdesc[d + 0];
            a1 += w[d + 1] * sdesc[d + 1];
            a2 += w[d + 2] * sdesc[d + 2];
            a3 += w[d + 3] * sdesc[d + 3];
        }
        float h = tanhf(a0 + a1 + a2 + a3);
        sh0[tid] = h;
        sa0[tid] = 1.f - h * h;
    }
    __syncthreads();

    // layer 1 + layer 2 partials
    {
        const float* w = W1 + (size_t)sp * DDIM * DDIM + (size_t)tid * DDIM;
        float a0 = b1[sp * DDIM + tid], a1 = 0.f, a2 = 0.f, a3 = 0.f;
        #pragma unroll
        for (int d = 0; d < DDIM; d += 4) {
            a0 += w[d + 0] * sh0[d + 0];
            a1 += w[d + 1] * sh0[d + 1];
            a2 += w[d + 2] * sh0[d + 2];
            a3 += w[d + 3] * sh0[d + 3];
        }
        float h = tanhf(a0 + a1 + a2 + a3);
        float w2v = W2[sp * DDIM + tid];
        sred[tid] = w2v * h;
        sd1[tid]  = w2v * (1.f - h * h);
    }
    __syncthreads();

    if (tid == 0) {
        float e = b2[sp];
        #pragma unroll 8
        for (int i = 0; i < DDIM; i++) e += sred[i];
        g_partial[(KDIM + NSTR) * NATOMS + n] = e;
    }

    // d0 = (W1^T @ d1) * (1 - h0^2)
    {
        const float* w = W1 + (size_t)sp * DDIM * DDIM + tid;
        float a0 = 0.f, a1 = 0.f;
        #pragma unroll 8
        for (int j = 0; j < DDIM; j += 2) {
            a0 += w[(size_t)(j + 0) * DDIM] * sd1[j + 0];
            a1 += w[(size_t)(j + 1) * DDIM] * sd1[j + 1];
        }
        __syncthreads();
        sa1[tid] = (a0 + a1) * sa0[tid];
    }
    __syncthreads();

    // G = W0^T @ d0
    {
        const float* w = W0 + (size_t)sp * DDIM * DDIM + tid;
        float a0 = 0.f, a1 = 0.f;
        #pragma unroll 8
        for (int j = 0; j < DDIM; j += 2) {
            a0 += w[(size_t)(j + 0) * DDIM] * sa1[j + 0];
            a1 += w[(size_t)(j + 1) * DDIM] * sa1[j + 1];
        }
        float g = a0 + a1;
        sG[tid] = g;
        g_G[n * DDIM + tid] = g;
    }
    __syncthreads();

    // stress partials: 6 rows of 128, warp per row
    const float4 gv = reinterpret_cast<const float4*>(sG)[lane];
    for (int r = wid; r < NSTR; r += 4) {
        const float4* row = reinterpret_cast<const float4*>(SG + ((size_t)n * NSTR + r) * DDIM);
        float4 v = row[lane];
        float s = v.x * gv.x + v.y * gv.y + v.z * gv.z + v.w * gv.w;
        #pragma unroll
        for (int off = 16; off > 0; off >>= 1)
            s += __shfl_xor_sync(0xFFFFFFFFu, s, off);
        if (lane == 0) g_partial[(size_t)(KDIM + r) * NATOMS + n] = s;
    }
}

// ---------------------------------------------------------------------------
// Kernel 2: stream coord_grads (403 MB, read-once).
//   grid = NATOMS * BLOCKS_PER_ATOM blocks of 256 threads.
//   Warp owns 32 consecutive k-rows; unroll x4 -> 4 independent loads in flight.
// ---------------------------------------------------------------------------
__global__ __launch_bounds__(STREAM_THREADS) void nnp_stream_kernel(
    const float* __restrict__ CG)     // [N, KDIM, D]
{
    const int b    = blockIdx.x;
    const int n    = b / BLOCKS_PER_ATOM;
    const int chnk = b % BLOCKS_PER_ATOM;
    const int wid  = threadIdx.x >> 5;
    const int lane = threadIdx.x & 31;

    const float4 gv = reinterpret_cast<const float4*>(g_G + (size_t)n * DDIM)[lane];

    const int k0 = chnk * 256 + wid * 32;   // 32 rows per warp
    const float4* base = reinterpret_cast<const float4*>(
        CG + ((size_t)n * KDIM + k0) * DDIM);
    float* outp = g_partial + (size_t)k0 * NATOMS + n;

    #pragma unroll
    for (int it = 0; it < 8; it++) {
        const float4* p = base + (size_t)(it * 4) * 32 + lane;
        float4 v0 = __ldcs(p + 0 * 32);
        float4 v1 = __ldcs(p + 1 * 32);
        float4 v2 = __ldcs(p + 2 * 32);
        float4 v3 = __ldcs(p + 3 * 32);
        float s0 = v0.x * gv.x + v0.y * gv.y + v0.z * gv.z + v0.w * gv.w;
        float s1 = v1.x * gv.x + v1.y * gv.y + v1.z * gv.z + v1.w * gv.w;
        float s2 = v2.x * gv.x + v2.y * gv.y + v2.z * gv.z + v2.w * gv.w;
        float s3 = v3.x * gv.x + v3.y * gv.y + v3.z * gv.z + v3.w * gv.w;
        #pragma unroll
        for (int off = 16; off > 0; off >>= 1) {
            s0 += __shfl_xor_sync(0xFFFFFFFFu, s0, off);
            s1 += __shfl_xor_sync(0xFFFFFFFFu, s1, off);
            s2 += __shfl_xor_sync(0xFFFFFFFFu, s2, off);
            s3 += __shfl_xor_sync(0xFFFFFFFFu, s3, off);
        }
        if (lane == 0) {
            outp[(size_t)(it * 4 + 0) * NATOMS] = s0;
            outp[(size_t)(it * 4 + 1) * NATOMS] = s1;
            outp[(size_t)(it * 4 + 2) * NATOMS] = s2;
            outp[(size_t)(it * 4 + 3) * NATOMS] = s3;
        }
    }
}

// ---------------------------------------------------------------------------
// Kernel 3: deterministic reduce over atoms. warp per output slot.
// ---------------------------------------------------------------------------
__global__ void nnp_reduce_kernel(float* __restrict__ out,
                                  const float* __restrict__ volume)
{
    const int k    = blockIdx.x * 8 + (threadIdx.x >> 5);
    const int lane = threadIdx.x & 31;
    if (k >= KTOT) return;

    const float4* base = reinterpret_cast<const float4*>(g_partial + (size_t)k * NATOMS);
    float4 v0 = base[lane + 0 * 32];
    float4 v1 = base[lane + 1 * 32];
    float4 v2 = base[lane + 2 * 32];
    float4 v3 = base[lane + 3 * 32];
    float s = (v0.x + v0.y + v0.z + v0.w) + (v1.x + v1.y + v1.z + v1.w)
            + (v2.x + v2.y + v2.z + v2.w) + (v3.x + v3.y + v3.z + v3.w);
    #pragma unroll
    for (int off = 16; off > 0; off >>= 1)
        s += __shfl_xor_sync(0xFFFFFFFFu, s, off);

    if (lane == 0) {
        if (k < KDIM)             out[1 + k] = s;                               // forces
        else if (k < KDIM + NSTR) out[1 + KDIM + (k - KDIM)] = -s / volume[0];  // stress
        else                      out[0] = s;                                   // energy
    }
}

extern "C" void kernel_launch(void* const* d_in, const int* in_sizes, int n_in,
                              void* d_out, int out_size)
{
    const float* desc    = (const float*)d_in[0];
    const float* CG      = (const float*)d_in[1];
    const float* SG      = (const float*)d_in[2];
    const float* W0      = (const float*)d_in[3];
    const float* b0      = (const float*)d_in[4];
    const float* W1      = (const float*)d_in[5];
    const float* b1      = (const float*)d_in[6];
    const float* W2      = (const float*)d_in[7];
    const float* b2      = (const float*)d_in[8];
    const float* volume  = (const float*)d_in[9];
    const int*   species = (const int*)  d_in[10];
    float* out = (float*)d_out;

    nnp_mlp_kernel<<<NATOMS, 128>>>(desc, SG, W0, b0, W1, b1, W2, b2, species);
    nnp_stream_kernel<<<NATOMS * BLOCKS_PER_ATOM, STREAM_THREADS>>>(CG);
    nnp_reduce_kernel<<<(KTOT + 7) / 8, 256>>>(out, volume);
}

// round 3
// speedup vs baseline: 1.5389x; 1.4045x over previous
#include <cuda_runtime.h>
#include <cstddef>

#define NATOMS 512
#define DDIM   128
#define KDIM   1536   // 3*N
#define NSTR   6
#define NCHUNK 4
#define CHUNK_ATOMS (NATOMS / NCHUNK)   // 128

// Scratch: force partials per (chunk, k) + per-atom stress/energy partials + G.
__device__ __align__(16) float g_fpart[NCHUNK * KDIM];        // 24 KB
__device__ __align__(16) float g_separt[(NSTR + 1) * NATOMS]; // 14 KB
__device__ __align__(16) float g_G[NATOMS * DDIM];            // 256 KB

// ---------------------------------------------------------------------------
// Kernel 1: per-atom species MLP forward + backward. Block per atom, 128 thr.
//   Forward matvecs: warp computes 4 rows at once, 8 lanes per row
//   (fully-coalesced 128B-line loads, 3-shuffle reduce).
//   Backward matvecs: thread-per-output column reads (coalesced).
// ---------------------------------------------------------------------------
__global__ __launch_bounds__(128) void nnp_mlp_kernel(
    const float* __restrict__ desc,   // [N, D]
    const float* __restrict__ SG,     // [N, 6, D]
    const float* __restrict__ W0,     // [S, H, D]
    const float* __restrict__ b0,     // [S, H]
    const float* __restrict__ W1,     // [S, H, H]
    const float* __restrict__ b1,     // [S, H]
    const float* __restrict__ W2,     // [S, 1, H]
    const float* __restrict__ b2,     // [S, 1]
    const int*   __restrict__ species)
{
    const int n    = blockIdx.x;
    const int tid  = threadIdx.x;
    const int wid  = tid >> 5;
    const int lane = tid & 31;
    const int rg   = lane >> 3;   // row-group 0..3 within warp
    const int l8   = lane & 7;    // lane within 8-lane row team

    __shared__ __align__(16) float sdesc[DDIM];
    __shared__ __align__(16) float sh0[DDIM];
    __shared__ __align__(16) float sa0[DDIM];
    __shared__ __align__(16) float sd1[DDIM];
    __shared__ __align__(16) float sa1[DDIM];
    __shared__ __align__(16) float sred[DDIM];
    __shared__ __align__(16) float sG[DDIM];

    const int sp = species[n];
    sdesc[tid] = desc[n * DDIM + tid];
    __syncthreads();

    // ---- layer 0 forward: h0 = tanh(W0 @ desc + b0) ----
    {
        const float* w0 = W0 + (size_t)sp * DDIM * DDIM;
        const float4* x4 = reinterpret_cast<const float4*>(sdesc);
        float4 xx0 = x4[l8 + 0 * 8], xx1 = x4[l8 + 1 * 8];
        float4 xx2 = x4[l8 + 2 * 8], xx3 = x4[l8 + 3 * 8];
        #pragma unroll
        for (int it = 0; it < 8; it++) {
            const int r = wid * 32 + it * 4 + rg;
            const float4* wr = reinterpret_cast<const float4*>(w0 + (size_t)r * DDIM);
            float4 w_0 = wr[l8 + 0 * 8], w_1 = wr[l8 + 1 * 8];
            float4 w_2 = wr[l8 + 2 * 8], w_3 = wr[l8 + 3 * 8];
            float a = w_0.x * xx0.x + w_0.y * xx0.y + w_0.z * xx0.z + w_0.w * xx0.w
                    + w_1.x * xx1.x + w_1.y * xx1.y + w_1.z * xx1.z + w_1.w * xx1.w
                    + w_2.x * xx2.x + w_2.y * xx2.y + w_2.z * xx2.z + w_2.w * xx2.w
                    + w_3.x * xx3.x + w_3.y * xx3.y + w_3.z * xx3.z + w_3.w * xx3.w;
            a += __shfl_xor_sync(0xFFFFFFFFu, a, 4);
            a += __shfl_xor_sync(0xFFFFFFFFu, a, 2);
            a += __shfl_xor_sync(0xFFFFFFFFu, a, 1);
            if (l8 == 0) {
                float h = tanhf(a + b0[sp * DDIM + r]);
                sh0[r] = h;
                sa0[r] = 1.f - h * h;
            }
        }
    }
    __syncthreads();

    // ---- layer 1 forward + output-layer partials ----
    {
        const float* w1 = W1 + (size_t)sp * DDIM * DDIM;
        const float4* x4 = reinterpret_cast<const float4*>(sh0);
        float4 xx0 = x4[l8 + 0 * 8], xx1 = x4[l8 + 1 * 8];
        float4 xx2 = x4[l8 + 2 * 8], xx3 = x4[l8 + 3 * 8];
        #pragma unroll
        for (int it = 0; it < 8; it++) {
            const int r = wid * 32 + it * 4 + rg;
            const float4* wr = reinterpret_cast<const float4*>(w1 + (size_t)r * DDIM);
            float4 w_0 = wr[l8 + 0 * 8], w_1 = wr[l8 + 1 * 8];
            float4 w_2 = wr[l8 + 2 * 8], w_3 = wr[l8 + 3 * 8];
            float a = w_0.x * xx0.x + w_0.y * xx0.y + w_0.z * xx0.z + w_0.w * xx0.w
                    + w_1.x * xx1.x + w_1.y * xx1.y + w_1.z * xx1.z + w_1.w * xx1.w
                    + w_2.x * xx2.x + w_2.y * xx2.y + w_2.z * xx2.z + w_2.w * xx2.w
                    + w_3.x * xx3.x + w_3.y * xx3.y + w_3.z * xx3.z + w_3.w * xx3.w;
            a += __shfl_xor_sync(0xFFFFFFFFu, a, 4);
            a += __shfl_xor_sync(0xFFFFFFFFu, a, 2);
            a += __shfl_xor_sync(0xFFFFFFFFu, a, 1);
            if (l8 == 0) {
                float h = tanhf(a + b1[sp * DDIM + r]);
                float w2v = W2[sp * DDIM + r];
                sred[r] = w2v * h;
                sd1[r]  = w2v * (1.f - h * h);
            }
        }
    }
    __syncthreads();

    // ---- energy partial (warp 0) ----
    if (wid == 0) {
        float4 e4 = reinterpret_cast<const float4*>(sred)[lane];
        float e = e4.x + e4.y + e4.z + e4.w;
        #pragma unroll
        for (int off = 16; off > 0; off >>= 1)
            e += __shfl_xor_sync(0xFFFFFFFFu, e, off);
        if (lane == 0) g_separt[NSTR * NATOMS + n] = e + b2[sp];
    }

    // ---- backward: d0 = (W1^T @ d1) * (1 - h0^2) ----
    {
        const float* w = W1 + (size_t)sp * DDIM * DDIM + tid;
        float a0 = 0.f, a1 = 0.f;
        #pragma unroll 8
        for (int j = 0; j < DDIM; j += 2) {
            a0 += w[(size_t)(j + 0) * DDIM] * sd1[j + 0];
            a1 += w[(size_t)(j + 1) * DDIM] * sd1[j + 1];
        }
        __syncthreads();
        sa1[tid] = (a0 + a1) * sa0[tid];
    }
    __syncthreads();

    // ---- backward: G = W0^T @ d0 ----
    {
        const float* w = W0 + (size_t)sp * DDIM * DDIM + tid;
        float a0 = 0.f, a1 = 0.f;
        #pragma unroll 8
        for (int j = 0; j < DDIM; j += 2) {
            a0 += w[(size_t)(j + 0) * DDIM] * sa1[j + 0];
            a1 += w[(size_t)(j + 1) * DDIM] * sa1[j + 1];
        }
        float g = a0 + a1;
        sG[tid] = g;
        g_G[n * DDIM + tid] = g;
    }
    __syncthreads();

    // ---- stress partials: 6 rows, warp per row ----
    {
        const float4 gv = reinterpret_cast<const float4*>(sG)[lane];
        for (int r = wid; r < NSTR; r += 4) {
            const float4* row = reinterpret_cast<const float4*>(
                SG + ((size_t)n * NSTR + r) * DDIM);
            float4 v = row[lane];
            float s = v.x * gv.x + v.y * gv.y + v.z * gv.z + v.w * gv.w;
            #pragma unroll
            for (int off = 16; off > 0; off >>= 1)
                s += __shfl_xor_sync(0xFFFFFFFFu, s, off);
            if (lane == 0) g_separt[(size_t)r * NATOMS + n] = s;
        }
    }
}

// ---------------------------------------------------------------------------
// Kernel 2: stream coord_grads (403 MB). k-major: warp owns (k-row, atom
// chunk of 128) and accumulates the dot over atoms in registers.
// grid = KDIM*NCHUNK/8 = 768 blocks x 256 threads.
// ---------------------------------------------------------------------------
__global__ __launch_bounds__(256) void nnp_stream_kernel(
    const float* __restrict__ CG)     // [N, KDIM, D]
{
    const int gw    = blockIdx.x * 8 + (threadIdx.x >> 5);
    const int lane  = threadIdx.x & 31;
    const int k     = gw >> 2;          // 0..1535
    const int chunk = gw & 3;           // 0..3

    const float4* G4  = reinterpret_cast<const float4*>(g_G);
    const float4* CG4 = reinterpret_cast<const float4*>(CG);
    const size_t stride = (size_t)KDIM * 32;   // float4 stride per atom

    float a0 = 0.f, a1 = 0.f, a2 = 0.f, a3 = 0.f;
    const int nbase = chunk * CHUNK_ATOMS;

    for (int i = 0; i < CHUNK_ATOMS; i += 4) {
        const int n = nbase + i;
        const size_t ridx = ((size_t)n * KDIM + k) * 32 + lane;
        float4 v0 = __ldcs(CG4 + ridx + 0 * stride);
        float4 v1 = __ldcs(CG4 + ridx + 1 * stride);
        float4 v2 = __ldcs(CG4 + ridx + 2 * stride);
        float4 v3 = __ldcs(CG4 + ridx + 3 * stride);
        float4 g0 = __ldg(G4 + (size_t)(n + 0) * 32 + lane);
        float4 g1 = __ldg(G4 + (size_t)(n + 1) * 32 + lane);
        float4 g2 = __ldg(G4 + (size_t)(n + 2) * 32 + lane);
        float4 g3 = __ldg(G4 + (size_t)(n + 3) * 32 + lane);
        a0 += v0.x * g0.x + v0.y * g0.y + v0.z * g0.z + v0.w * g0.w;
        a1 += v1.x * g1.x + v1.y * g1.y + v1.z * g1.z + v1.w * g1.w;
        a2 += v2.x * g2.x + v2.y * g2.y + v2.z * g2.z + v2.w * g2.w;
        a3 += v3.x * g3.x + v3.y * g3.y + v3.z * g3.z + v3.w * g3.w;
    }
    float s = (a0 + a1) + (a2 + a3);
    #pragma unroll
    for (int off = 16; off > 0; off >>= 1)
        s += __shfl_xor_sync(0xFFFFFFFFu, s, off);
    if (lane == 0) g_fpart[chunk * KDIM + k] = s;
}

// ---------------------------------------------------------------------------
// Kernel 3: finalize. Forces: sum 4 chunk partials per k. Stress/energy:
// warp per slot over 512 atom partials. grid = 7 x 256.
// ---------------------------------------------------------------------------
__global__ __launch_bounds__(256) void nnp_finalize_kernel(
    float* __restrict__ out, const float* __restrict__ volume)
{
    const int t = blockIdx.x * 256 + threadIdx.x;
    if (t < KDIM) {
        out[1 + t] = (g_fpart[t] + g_fpart[KDIM + t])
                   + (g_fpart[2 * KDIM + t] + g_fpart[3 * KDIM + t]);
    } else if (t < KDIM + 256) {
        const int w    = (t - KDIM) >> 5;
        const int lane = t & 31;
        if (w < NSTR + 1) {
            const float4* base = reinterpret_cast<const float4*>(
                g_separt + (size_t)w * NATOMS);
            float4 v0 = base[lane + 0 * 32];
            float4 v1 = base[lane + 1 * 32];
            float4 v2 = base[lane + 2 * 32];
            float4 v3 = base[lane + 3 * 32];
            float s = (v0.x + v0.y + v0.z + v0.w) + (v1.x + v1.y + v1.z + v1.w)
                    + (v2.x + v2.y + v2.z + v2.w) + (v3.x + v3.y + v3.z + v3.w);
            #pragma unroll
            for (int off = 16; off > 0; off >>= 1)
                s += __shfl_xor_sync(0xFFFFFFFFu, s, off);
            if (lane == 0) {
                if (w < NSTR) out[1 + KDIM + w] = -s / volume[0];
                else          out[0] = s;
            }
        }
    }
}

extern "C" void kernel_launch(void* const* d_in, const int* in_sizes, int n_in,
                              void* d_out, int out_size)
{
    const float* desc    = (const float*)d_in[0];
    const float* CG      = (const float*)d_in[1];
    const float* SG      = (const float*)d_in[2];
    const float* W0      = (const float*)d_in[3];
    const float* b0      = (const float*)d_in[4];
    const float* W1      = (const float*)d_in[5];
    const float* b1      = (const float*)d_in[6];
    const float* W2      = (const float*)d_in[7];
    const float* b2      = (const float*)d_in[8];
    const float* volume  = (const float*)d_in[9];
    const int*   species = (const int*)  d_in[10];
    float* out = (float*)d_out;

    nnp_mlp_kernel<<<NATOMS, 128>>>(desc, SG, W0, b0, W1, b1, W2, b2, species);
    nnp_stream_kernel<<<(KDIM * NCHUNK) / 8, 256>>>(CG);
    nnp_finalize_kernel<<<7, 256>>>(out, volume);
}

// round 4
// speedup vs baseline: 1.7130x; 1.1132x over previous
#include <cuda_runtime.h>
#include <cstddef>

#define NATOMS 512
#define DDIM   128
#define KDIM   1536   // 3*N
#define NSTR   6
#define KTOT   (KDIM + NSTR + 1)
#define NSPEC  4
#define TILE   16     // atoms per MLP block
#define XS     132    // padded smem row stride (floats), conflict-free

// Scratch
__device__ __align__(16) float g_partial[KDIM * NATOMS];        // force partials (3 MB)
__device__ __align__(16) float g_separt[(NSTR + 1) * NATOMS];   // stress + energy partials
__device__ __align__(16) float g_G[NATOMS * DDIM];              // per-atom dE/ddesc
__device__ int g_list[NSPEC * NATOMS];
__device__ int g_cnt[NSPEC];

// ---------------------------------------------------------------------------
// Kernel 0: build per-species atom lists (order-independent).
// ---------------------------------------------------------------------------
__global__ __launch_bounds__(NATOMS) void nnp_setup_kernel(const int* __restrict__ species)
{
    __shared__ int cnt[NSPEC];
    const int t = threadIdx.x;
    if (t < NSPEC) cnt[t] = 0;
    __syncthreads();
    const int sp = species[t];
    const int pos = atomicAdd(&cnt[sp], 1);
    g_list[sp * NATOMS + pos] = t;
    __syncthreads();
    if (t < NSPEC) g_cnt[t] = cnt[t];
}

// ---------------------------------------------------------------------------
// Kernel 1: species-batched MLP fwd+bwd. Block = (species s, 16-atom tile).
// Whole W0[s], W1[s] staged in smem; register-tiled 128x16 matvec batches.
// Thread (ty,tx): ty=tid/16 -> 8 output rows, tx=tid%16 -> atom.
// ---------------------------------------------------------------------------
__global__ __launch_bounds__(256) void nnp_mlp_kernel(
    const float* __restrict__ desc,   // [N, D]
    const float* __restrict__ SG,     // [N, 6, D]
    const float* __restrict__ W0,     // [S, H, D]
    const float* __restrict__ b0,     // [S, H]
    const float* __restrict__ W1,     // [S, H, H]
    const float* __restrict__ b1,     // [S, H]
    const float* __restrict__ W2,     // [S, 1, H]
    const float* __restrict__ b2)     // [S, 1]
{
    const int s = blockIdx.y;
    const int j = blockIdx.x;
    const int cnt = g_cnt[s];
    if (j * TILE >= cnt) return;
    const int m = min(TILE, cnt - j * TILE);

    const int tid = threadIdx.x;
    const int ty  = tid >> 4;    // 0..15
    const int tx  = tid & 15;    // 0..15 (atom)
    const int wid = tid >> 5;
    const int lane = tid & 31;

    extern __shared__ float sm[];
    float* W0s = sm;                    // 16384
    float* W1s = sm + 16384;            // 16384
    float* X   = sm + 32768;            // TILE*XS  (descriptors)
    float* H0  = X  + TILE * XS;        // TILE*XS  (h0, later G)
    float* A0  = H0 + TILE * XS;        // TILE*XS  (1-h0^2, later d0)
    float* D1  = A0 + TILE * XS;        // TILE*XS
    float* Ep  = D1 + TILE * XS;        // 256 energy partials
    __shared__ int idx[TILE];

    if (tid < TILE) idx[tid] = (tid < m) ? g_list[s * NATOMS + j * TILE + tid] : 0;
    __syncthreads();

    // stage descriptors (zero-pad inactive atoms) and full W0/W1
    for (int e = tid; e < TILE * DDIM; e += 256) {
        const int a = e >> 7, d = e & 127;
        X[a * XS + d] = (a < m) ? desc[(size_t)idx[a] * DDIM + d] : 0.f;
    }
    {
        const float4* w0g = (const float4*)(W0 + (size_t)s * DDIM * DDIM);
        const float4* w1g = (const float4*)(W1 + (size_t)s * DDIM * DDIM);
        float4* w0s = (float4*)W0s;
        float4* w1s = (float4*)W1s;
        for (int f = tid; f < 4096; f += 256) { w0s[f] = w0g[f]; w1s[f] = w1g[f]; }
    }
    __syncthreads();

    // ---- forward layer 0: H0 = tanh(W0 @ X + b0) ----
    {
        float acc[8] = {0,0,0,0,0,0,0,0};
        const float4* X4 = (const float4*)(X + tx * XS);
        const float4* W4 = (const float4*)W0s;
        #pragma unroll 4
        for (int dq = 0; dq < 32; dq++) {
            const float4 xv = X4[dq];
            #pragma unroll
            for (int i = 0; i < 8; i++) {
                const float4 wv = W4[(ty * 8 + i) * 32 + dq];
                acc[i] += wv.x * xv.x + wv.y * xv.y + wv.z * xv.z + wv.w * xv.w;
            }
        }
        #pragma unroll
        for (int i = 0; i < 8; i++) {
            const int r = ty * 8 + i;
            const float h = tanhf(acc[i] + b0[s * DDIM + r]);
            H0[tx * XS + r] = h;
            A0[tx * XS + r] = 1.f - h * h;
        }
    }
    __syncthreads();

    // ---- forward layer 1: h1 = tanh(W1 @ H0 + b1); D1 = W2*(1-h1^2); Ep ----
    {
        float acc[8] = {0,0,0,0,0,0,0,0};
        const float4* X4 = (const float4*)(H0 + tx * XS);
        const float4* W4 = (const float4*)W1s;
        #pragma unroll 4
        for (int dq = 0; dq < 32; dq++) {
            const float4 xv = X4[dq];
            #pragma unroll
            for (int i = 0; i < 8; i++) {
                const float4 wv = W4[(ty * 8 + i) * 32 + dq];
                acc[i] += wv.x * xv.x + wv.y * xv.y + wv.z * xv.z + wv.w * xv.w;
            }
        }
        float ep = 0.f;
        #pragma unroll
        for (int i = 0; i < 8; i++) {
            const int r = ty * 8 + i;
            const float h = tanhf(acc[i] + b1[s * DDIM + r]);
            const float w2v = W2[s * DDIM + r];
            ep += w2v * h;
            D1[tx * XS + r] = w2v * (1.f - h * h);
        }
        Ep[ty * 16 + tx] = ep;
    }
    __syncthreads();

    // ---- energy per atom ----
    if (tid < m) {
        float e = b2[s];
        #pragma unroll
        for (int t2 = 0; t2 < 16; t2++) e += Ep[t2 * 16 + tid];
        g_separt[NSTR * NATOMS + idx[tid]] = e;
    }

    // ---- backward: D0 = (W1^T @ D1) * A0   (in-place into A0) ----
    {
        float acc[8] = {0,0,0,0,0,0,0,0};
        const float* d1p = D1 + tx * XS;
        #pragma unroll 4
        for (int jj = 0; jj < DDIM; jj++) {
            const float dv = d1p[jj];
            const float4* W4 = (const float4*)(W1s + jj * DDIM + ty * 8);
            const float4 w0v = W4[0], w1v = W4[1];
            acc[0] += w0v.x * dv; acc[1] += w0v.y * dv;
            acc[2] += w0v.z * dv; acc[3] += w0v.w * dv;
            acc[4] += w1v.x * dv; acc[5] += w1v.y * dv;
            acc[6] += w1v.z * dv; acc[7] += w1v.w * dv;
        }
        #pragma unroll
        for (int i = 0; i < 8; i++)
            A0[tx * XS + ty * 8 + i] *= acc[i];     // element owned by this thread
    }
    __syncthreads();

    // ---- backward: G = W0^T @ D0  -> smem (H0 reused) + gmem g_G ----
    {
        float acc[8] = {0,0,0,0,0,0,0,0};
        const float* d0p = A0 + tx * XS;
        #pragma unroll 4
        for (int jj = 0; jj < DDIM; jj++) {
            const float dv = d0p[jj];
            const float4* W4 = (const float4*)(W0s + jj * DDIM + ty * 8);
            const float4 w0v = W4[0], w1v = W4[1];
            acc[0] += w0v.x * dv; acc[1] += w0v.y * dv;
            acc[2] += w0v.z * dv; acc[3] += w0v.w * dv;
            acc[4] += w1v.x * dv; acc[5] += w1v.y * dv;
            acc[6] += w1v.z * dv; acc[7] += w1v.w * dv;
        }
        #pragma unroll
        for (int i = 0; i < 8; i++) H0[tx * XS + ty * 8 + i] = acc[i];
        if (tx < m) {
            float4* gp = (float4*)(g_G + (size_t)idx[tx] * DDIM + ty * 8);
            gp[0] = make_float4(acc[0], acc[1], acc[2], acc[3]);
            gp[1] = make_float4(acc[4], acc[5], acc[6], acc[7]);
        }
    }
    __syncthreads();

    // ---- stress partials: 6 rows x m atoms, warp-dot each ----
    for (int t = wid; t < NSTR * m; t += 8) {
        const int a  = t / NSTR;
        const int rs = t % NSTR;
        const int n  = idx[a];
        const float4 v = ((const float4*)(SG + ((size_t)n * NSTR + rs) * DDIM))[lane];
        const float4 g = ((const float4*)(H0 + a * XS))[lane];
        float sv = v.x * g.x + v.y * g.y + v.z * g.z + v.w * g.w;
        #pragma unroll
        for (int off = 16; off > 0; off >>= 1)
            sv += __shfl_xor_sync(0xFFFFFFFFu, sv, off);
        if (lane == 0) g_separt[(size_t)rs * NATOMS + n] = sv;
    }
}

// ---------------------------------------------------------------------------
// Kernel 2: stream coord_grads (403 MB), atom-major (R2 layout — measured
// ~roofline). Warp owns 32 consecutive k-rows of one atom; x4 ILP, __ldcs.
// ---------------------------------------------------------------------------
__global__ __launch_bounds__(256) void nnp_stream_kernel(
    const float* __restrict__ CG)     // [N, KDIM, D]
{
    const int b    = blockIdx.x;
    const int n    = b / 6;
    const int chnk = b % 6;
    const int wid  = threadIdx.x >> 5;
    const int lane = threadIdx.x & 31;

    const float4 gv = reinterpret_cast<const float4*>(g_G + (size_t)n * DDIM)[lane];

    const int k0 = chnk * 256 + wid * 32;
    const float4* base = reinterpret_cast<const float4*>(
        CG + ((size_t)n * KDIM + k0) * DDIM);
    float* outp = g_partial + (size_t)k0 * NATOMS + n;

    #pragma unroll
    for (int it = 0; it < 8; it++) {
        const float4* p = base + (size_t)(it * 4) * 32 + lane;
        float4 v0 = __ldcs(p + 0 * 32);
        float4 v1 = __ldcs(p + 1 * 32);
        float4 v2 = __ldcs(p + 2 * 32);
        float4 v3 = __ldcs(p + 3 * 32);
        float s0 = v0.x * gv.x + v0.y * gv.y + v0.z * gv.z + v0.w * gv.w;
        float s1 = v1.x * gv.x + v1.y * gv.y + v1.z * gv.z + v1.w * gv.w;
        float s2 = v2.x * gv.x + v2.y * gv.y + v2.z * gv.z + v2.w * gv.w;
        float s3 = v3.x * gv.x + v3.y * gv.y + v3.z * gv.z + v3.w * gv.w;
        #pragma unroll
        for (int off = 16; off > 0; off >>= 1) {
            s0 += __shfl_xor_sync(0xFFFFFFFFu, s0, off);
            s1 += __shfl_xor_sync(0xFFFFFFFFu, s1, off);
            s2 += __shfl_xor_sync(0xFFFFFFFFu, s2, off);
            s3 += __shfl_xor_sync(0xFFFFFFFFu, s3, off);
        }
        if (lane == 0) {
            outp[(size_t)(it * 4 + 0) * NATOMS] = s0;
            outp[(size_t)(it * 4 + 1) * NATOMS] = s1;
            outp[(size_t)(it * 4 + 2) * NATOMS] = s2;
            outp[(size_t)(it * 4 + 3) * NATOMS] = s3;
        }
    }
}

// ---------------------------------------------------------------------------
// Kernel 3: deterministic reduce. Warp per output slot over 512 atoms.
// ---------------------------------------------------------------------------
__global__ void nnp_reduce_kernel(float* __restrict__ out,
                                  const float* __restrict__ volume)
{
    const int k    = blockIdx.x * 8 + (threadIdx.x >> 5);
    const int lane = threadIdx.x & 31;
    if (k >= KTOT) return;

    const float* src = (k < KDIM) ? (g_partial + (size_t)k * NATOMS)
                                  : (g_separt + (size_t)(k - KDIM) * NATOMS);
    const float4* base = reinterpret_cast<const float4*>(src);
    float4 v0 = base[lane + 0 * 32];
    float4 v1 = base[lane + 1 * 32];
    float4 v2 = base[lane + 2 * 32];
    float4 v3 = base[lane + 3 * 32];
    float s = (v0.x + v0.y + v0.z + v0.w) + (v1.x + v1.y + v1.z + v1.w)
            + (v2.x + v2.y + v2.z + v2.w) + (v3.x + v3.y + v3.z + v3.w);
    #pragma unroll
    for (int off = 16; off > 0; off >>= 1)
        s += __shfl_xor_sync(0xFFFFFFFFu, s, off);

    if (lane == 0) {
        if (k < KDIM)             out[1 + k] = s;                               // forces
        else if (k < KDIM + NSTR) out[1 + KDIM + (k - KDIM)] = -s / volume[0];  // stress
        else                      out[0] = s;                                   // energy
    }
}

extern "C" void kernel_launch(void* const* d_in, const int* in_sizes, int n_in,
                              void* d_out, int out_size)
{
    const float* desc    = (const float*)d_in[0];
    const float* CG      = (const float*)d_in[1];
    const float* SG      = (const float*)d_in[2];
    const float* W0      = (const float*)d_in[3];
    const float* b0      = (const float*)d_in[4];
    const float* W1      = (const float*)d_in[5];
    const float* b1      = (const float*)d_in[6];
    const float* W2      = (const float*)d_in[7];
    const float* b2      = (const float*)d_in[8];
    const float* volume  = (const float*)d_in[9];
    const int*   species = (const int*)  d_in[10];
    float* out = (float*)d_out;

    const int mlp_smem = (32768 + 4 * TILE * XS + 256) * sizeof(float);  // ~166 KB
    static bool attr_set = false;
    if (!attr_set) {
        cudaFuncSetAttribute(nnp_mlp_kernel,
                             cudaFuncAttributeMaxDynamicSharedMemorySize, mlp_smem);
        attr_set = true;
    }

    nnp_setup_kernel<<<1, NATOMS>>>(species);
    dim3 mlp_grid(NATOMS / TILE, NSPEC);
    nnp_mlp_kernel<<<mlp_grid, 256, mlp_smem>>>(desc, SG, W0, b0, W1, b1, W2, b2);
    nnp_stream_kernel<<<NATOMS * 6, 256>>>(CG);
    nnp_reduce_kernel<<<(KTOT + 7) / 8, 256>>>(out, volume);
}

// round 5
// speedup vs baseline: 1.8447x; 1.0769x over previous
#include <cuda_runtime.h>
#include <cstddef>

#define NATOMS 512
#define DDIM   128
#define KDIM   1536   // 3*N
#define NSTR   6
#define KTOT   (KDIM + NSTR + 1)
#define NSPEC  4
#define TILE   8      // atoms per MLP block
#define XS     132    // padded smem row stride (floats)

typedef unsigned long long u64;

// fma.rn.f32x2: packed 2xf32 FMA (sm_100+), not emitted by ptxas from C++.
#define FMA_F32X2(d, a, b, c) \
    asm("fma.rn.f32x2 %0, %1, %2, %3;" : "=l"(d) : "l"(a), "l"(b), "l"(c))
#define PACK_F32X2(out, lo, hi) \
    asm("mov.b64 %0, {%1, %2};" : "=l"(out) : "r"(__float_as_uint(lo)), "r"(__float_as_uint(hi)))

__device__ __forceinline__ float f32x2_lo(u64 v) { return __uint_as_float((unsigned)(v & 0xFFFFFFFFu)); }
__device__ __forceinline__ float f32x2_hi(u64 v) { return __uint_as_float((unsigned)(v >> 32)); }
__device__ __forceinline__ float f32x2_sum(u64 v) { return f32x2_lo(v) + f32x2_hi(v); }

// Scratch
__device__ __align__(16) float g_partial[KDIM * NATOMS];        // force partials (3 MB)
__device__ __align__(16) float g_separt[(NSTR + 1) * NATOMS];   // stress + energy partials
__device__ __align__(16) float g_G[NATOMS * DDIM];              // per-atom dE/ddesc
__device__ int g_list[NSPEC * NATOMS];
__device__ int g_cnt[NSPEC];

// ---------------------------------------------------------------------------
// Kernel 0: per-species atom lists (order-independent).
// ---------------------------------------------------------------------------
__global__ __launch_bounds__(NATOMS) void nnp_setup_kernel(const int* __restrict__ species)
{
    __shared__ int cnt[NSPEC];
    const int t = threadIdx.x;
    if (t < NSPEC) cnt[t] = 0;
    __syncthreads();
    const int sp = species[t];
    const int pos = atomicAdd(&cnt[sp], 1);
    g_list[sp * NATOMS + pos] = t;
    __syncthreads();
    if (t < NSPEC) g_cnt[t] = cnt[t];
}

// ---------------------------------------------------------------------------
// Kernel 1: species-batched MLP fwd+bwd. Block = (species, 8-atom tile).
// W0[s], W1[s] staged in smem. Thread (ty,tx): ty=tid>>3 -> 4 output rows,
// tx=tid&7 -> atom. All matvec passes use packed fma.rn.f32x2.
// ---------------------------------------------------------------------------
__global__ __launch_bounds__(256) void nnp_mlp_kernel(
    const float* __restrict__ desc,   // [N, D]
    const float* __restrict__ SG,     // [N, 6, D]
    const float* __restrict__ W0,     // [S, H, D]
    const float* __restrict__ b0,     // [S, H]
    const float* __restrict__ W1,     // [S, H, H]
    const float* __restrict__ b1,     // [S, H]
    const float* __restrict__ W2,     // [S, 1, H]
    const float* __restrict__ b2)     // [S, 1]
{
    const int s = blockIdx.y;
    const int j = blockIdx.x;
    const int cnt = g_cnt[s];
    if (j * TILE >= cnt) return;
    const int m = min(TILE, cnt - j * TILE);

    const int tid = threadIdx.x;
    const int ty  = tid >> 3;     // 0..31 -> rows ty*4 .. ty*4+3
    const int tx  = tid & 7;      // atom within tile
    const int wid = tid >> 5;
    const int lane = tid & 31;
    const int rbase = ty * 4;

    extern __shared__ float sm[];
    float* W0s = sm;                    // 16384
    float* W1s = sm + 16384;            // 16384
    float* X   = sm + 32768;            // TILE*XS
    float* H0  = X  + TILE * XS;        // h0, later G
    float* A0  = H0 + TILE * XS;        // 1-h0^2, later d0
    float* D1  = A0 + TILE * XS;
    float* Ep  = D1 + TILE * XS;        // 256
    __shared__ int idx[TILE];

    if (tid < TILE) idx[tid] = (tid < m) ? g_list[s * NATOMS + j * TILE + tid] : 0;
    __syncthreads();

    for (int e = tid; e < TILE * DDIM; e += 256) {
        const int a = e >> 7, d = e & 127;
        X[a * XS + d] = (a < m) ? desc[(size_t)idx[a] * DDIM + d] : 0.f;
    }
    {
        const float4* w0g = (const float4*)(W0 + (size_t)s * DDIM * DDIM);
        const float4* w1g = (const float4*)(W1 + (size_t)s * DDIM * DDIM);
        float4* w0s = (float4*)W0s;
        float4* w1s = (float4*)W1s;
        for (int f = tid; f < 4096; f += 256) { w0s[f] = w0g[f]; w1s[f] = w1g[f]; }
    }
    __syncthreads();

    // ---- forward layer 0: H0 = tanh(W0 @ X + b0) ----
    {
        u64 acc[4] = {0ull, 0ull, 0ull, 0ull};
        const u64* Xd = (const u64*)(X + tx * XS);
        const u64* Wd = (const u64*)W0s;
        #pragma unroll 8
        for (int dq = 0; dq < 64; dq++) {
            const u64 xv = Xd[dq];
            FMA_F32X2(acc[0], Wd[(size_t)(rbase + 0) * 64 + dq], xv, acc[0]);
            FMA_F32X2(acc[1], Wd[(size_t)(rbase + 1) * 64 + dq], xv, acc[1]);
            FMA_F32X2(acc[2], Wd[(size_t)(rbase + 2) * 64 + dq], xv, acc[2]);
            FMA_F32X2(acc[3], Wd[(size_t)(rbase + 3) * 64 + dq], xv, acc[3]);
        }
        #pragma unroll
        for (int i = 0; i < 4; i++) {
            const int r = rbase + i;
            const float h = tanhf(f32x2_sum(acc[i]) + b0[s * DDIM + r]);
            H0[tx * XS + r] = h;
            A0[tx * XS + r] = 1.f - h * h;
        }
    }
    __syncthreads();

    // ---- forward layer 1 + output-layer partials ----
    {
        u64 acc[4] = {0ull, 0ull, 0ull, 0ull};
        const u64* Xd = (const u64*)(H0 + tx * XS);
        const u64* Wd = (const u64*)W1s;
        #pragma unroll 8
        for (int dq = 0; dq < 64; dq++) {
            const u64 xv = Xd[dq];
            FMA_F32X2(acc[0], Wd[(size_t)(rbase + 0) * 64 + dq], xv, acc[0]);
            FMA_F32X2(acc[1], Wd[(size_t)(rbase + 1) * 64 + dq], xv, acc[1]);
            FMA_F32X2(acc[2], Wd[(size_t)(rbase + 2) * 64 + dq], xv, acc[2]);
            FMA_F32X2(acc[3], Wd[(size_t)(rbase + 3) * 64 + dq], xv, acc[3]);
        }
        float ep = 0.f;
        #pragma unroll
        for (int i = 0; i < 4; i++) {
            const int r = rbase + i;
            const float h = tanhf(f32x2_sum(acc[i]) + b1[s * DDIM + r]);
            const float w2v = W2[s * DDIM + r];
            ep += w2v * h;
            D1[tx * XS + r] = w2v * (1.f - h * h);
        }
        Ep[tid] = ep;   // tid == ty*8 + tx
    }
    __syncthreads();

    // ---- energy per atom ----
    if (tid < m) {
        float e = b2[s];
        #pragma unroll
        for (int t2 = 0; t2 < 32; t2++) e += Ep[t2 * 8 + tid];
        g_separt[NSTR * NATOMS + idx[tid]] = e;
    }

    // ---- backward: D0 = (W1^T @ D1) * A0 (in place, rows owned by thread) ----
    {
        u64 acc[2] = {0ull, 0ull};
        const float* d1p = D1 + tx * XS;
        #pragma unroll 4
        for (int jj = 0; jj < DDIM; jj++) {
            const float dv = d1p[jj];
            u64 dv2; PACK_F32X2(dv2, dv, dv);
            const u64* Wc = (const u64*)(W1s + (size_t)jj * DDIM + rbase);
            FMA_F32X2(acc[0], Wc[0], dv2, acc[0]);
            FMA_F32X2(acc[1], Wc[1], dv2, acc[1]);
        }
        A0[tx * XS + rbase + 0] *= f32x2_lo(acc[0]);
        A0[tx * XS + rbase + 1] *= f32x2_hi(acc[0]);
        A0[tx * XS + rbase + 2] *= f32x2_lo(acc[1]);
        A0[tx * XS + rbase + 3] *= f32x2_hi(acc[1]);
    }
    __syncthreads();

    // ---- backward: G = W0^T @ D0 -> H0 (reused) + g_G ----
    {
        u64 acc[2] = {0ull, 0ull};
        const float* d0p = A0 + tx * XS;
        #pragma unroll 4
        for (int jj = 0; jj < DDIM; jj++) {
            const float dv = d0p[jj];
            u64 dv2; PACK_F32X2(dv2, dv, dv);
            const u64* Wc = (const u64*)(W0s + (size_t)jj * DDIM + rbase);
            FMA_F32X2(acc[0], Wc[0], dv2, acc[0]);
            FMA_F32X2(acc[1], Wc[1], dv2, acc[1]);
        }
        const float g0 = f32x2_lo(acc[0]), g1 = f32x2_hi(acc[0]);
        const float g2 = f32x2_lo(acc[1]), g3 = f32x2_hi(acc[1]);
        H0[tx * XS + rbase + 0] = g0;
        H0[tx * XS + rbase + 1] = g1;
        H0[tx * XS + rbase + 2] = g2;
        H0[tx * XS + rbase + 3] = g3;
        if (tx < m)
            *(float4*)(g_G + (size_t)idx[tx] * DDIM + rbase) = make_float4(g0, g1, g2, g3);
    }
    __syncthreads();

    // ---- stress partials: warp per (atom, stress row) ----
    for (int t = wid; t < NSTR * m; t += 8) {
        const int a  = t / NSTR;
        const int rs = t % NSTR;
        const int n  = idx[a];
        const float4 v = ((const float4*)(SG + ((size_t)n * NSTR + rs) * DDIM))[lane];
        const float4 g = ((const float4*)(H0 + a * XS))[lane];
        float sv = v.x * g.x + v.y * g.y + v.z * g.z + v.w * g.w;
        #pragma unroll
        for (int off = 16; off > 0; off >>= 1)
            sv += __shfl_xor_sync(0xFFFFFFFFu, sv, off);
        if (lane == 0) g_separt[(size_t)rs * NATOMS + n] = sv;
    }
}

// ---------------------------------------------------------------------------
// Kernel 2: stream coord_grads (403 MB), atom-major — measured ~roofline.
// ---------------------------------------------------------------------------
__global__ __launch_bounds__(256) void nnp_stream_kernel(
    const float* __restrict__ CG)     // [N, KDIM, D]
{
    const int b    = blockIdx.x;
    const int n    = b / 6;
    const int chnk = b % 6;
    const int wid  = threadIdx.x >> 5;
    const int lane = threadIdx.x & 31;

    const float4 gv = reinterpret_cast<const float4*>(g_G + (size_t)n * DDIM)[lane];

    const int k0 = chnk * 256 + wid * 32;
    const float4* base = reinterpret_cast<const float4*>(
        CG + ((size_t)n * KDIM + k0) * DDIM);
    float* outp = g_partial + (size_t)k0 * NATOMS + n;

    #pragma unroll
    for (int it = 0; it < 8; it++) {
        const float4* p = base + (size_t)(it * 4) * 32 + lane;
        float4 v0 = __ldcs(p + 0 * 32);
        float4 v1 = __ldcs(p + 1 * 32);
        float4 v2 = __ldcs(p + 2 * 32);
        float4 v3 = __ldcs(p + 3 * 32);
        float s0 = v0.x * gv.x + v0.y * gv.y + v0.z * gv.z + v0.w * gv.w;
        float s1 = v1.x * gv.x + v1.y * gv.y + v1.z * gv.z + v1.w * gv.w;
        float s2 = v2.x * gv.x + v2.y * gv.y + v2.z * gv.z + v2.w * gv.w;
        float s3 = v3.x * gv.x + v3.y * gv.y + v3.z * gv.z + v3.w * gv.w;
        #pragma unroll
        for (int off = 16; off > 0; off >>= 1) {
            s0 += __shfl_xor_sync(0xFFFFFFFFu, s0, off);
            s1 += __shfl_xor_sync(0xFFFFFFFFu, s1, off);
            s2 += __shfl_xor_sync(0xFFFFFFFFu, s2, off);
            s3 += __shfl_xor_sync(0xFFFFFFFFu, s3, off);
        }
        if (lane == 0) {
            outp[(size_t)(it * 4 + 0) * NATOMS] = s0;
            outp[(size_t)(it * 4 + 1) * NATOMS] = s1;
            outp[(size_t)(it * 4 + 2) * NATOMS] = s2;
            outp[(size_t)(it * 4 + 3) * NATOMS] = s3;
        }
    }
}

// ---------------------------------------------------------------------------
// Kernel 3: deterministic reduce. Warp per output slot over 512 atoms.
// ---------------------------------------------------------------------------
__global__ void nnp_reduce_kernel(float* __restrict__ out,
                                  const float* __restrict__ volume)
{
    const int k    = blockIdx.x * 8 + (threadIdx.x >> 5);
    const int lane = threadIdx.x & 31;
    if (k >= KTOT) return;

    const float* src = (k < KDIM) ? (g_partial + (size_t)k * NATOMS)
                                  : (g_separt + (size_t)(k - KDIM) * NATOMS);
    const float4* base = reinterpret_cast<const float4*>(src);
    float4 v0 = base[lane + 0 * 32];
    float4 v1 = base[lane + 1 * 32];
    float4 v2 = base[lane + 2 * 32];
    float4 v3 = base[lane + 3 * 32];
    float s = (v0.x + v0.y + v0.z + v0.w) + (v1.x + v1.y + v1.z + v1.w)
            + (v2.x + v2.y + v2.z + v2.w) + (v3.x + v3.y + v3.z + v3.w);
    #pragma unroll
    for (int off = 16; off > 0; off >>= 1)
        s += __shfl_xor_sync(0xFFFFFFFFu, s, off);

    if (lane == 0) {
        if (k < KDIM)             out[1 + k] = s;
        else if (k < KDIM + NSTR) out[1 + KDIM + (k - KDIM)] = -s / volume[0];
        else                      out[0] = s;
    }
}

extern "C" void kernel_launch(void* const* d_in, const int* in_sizes, int n_in,
                              void* d_out, int out_size)
{
    const float* desc    = (const float*)d_in[0];
    const float* CG      = (const float*)d_in[1];
    const float* SG      = (const float*)d_in[2];
    const float* W0      = (const float*)d_in[3];
    const float* b0      = (const float*)d_in[4];
    const float* W1      = (const float*)d_in[5];
    const float* b1      = (const float*)d_in[6];
    const float* W2      = (const float*)d_in[7];
    const float* b2      = (const float*)d_in[8];
    const float* volume  = (const float*)d_in[9];
    const int*   species = (const int*)  d_in[10];
    float* out = (float*)d_out;

    const int mlp_smem = (32768 + 4 * TILE * XS + 256) * sizeof(float);  // ~148 KB
    cudaFuncSetAttribute(nnp_mlp_kernel,
                         cudaFuncAttributeMaxDynamicSharedMemorySize, mlp_smem);

    nnp_setup_kernel<<<1, NATOMS>>>(species);
    dim3 mlp_grid(NATOMS / TILE, NSPEC);
    nnp_mlp_kernel<<<mlp_grid, 256, mlp_smem>>>(desc, SG, W0, b0, W1, b1, W2, b2);
    nnp_stream_kernel<<<NATOMS * 6, 256>>>(CG);
    nnp_reduce_kernel<<<(KTOT + 7) / 8, 256>>>(out, volume);
}

// round 6
// speedup vs baseline: 1.8621x; 1.0094x over previous
#include <cuda_runtime.h>
#include <cstddef>

#define NATOMS 512
#define DDIM   128
#define KDIM   1536   // 3*N
#define NSTR   6
#define KTOT   (KDIM + NSTR + 1)
#define NSPEC  4
#define TILE   4      // atoms per MLP block
#define XS     132    // padded smem row stride (floats)
#define NTILES_MAX (NATOMS / TILE + NSPEC - 1)   // 131

typedef unsigned long long u64;

// fma.rn.f32x2: packed 2xf32 FMA (sm_100+), not emitted by ptxas from C++.
#define FMA_F32X2(d, a, b, c) \
    asm("fma.rn.f32x2 %0, %1, %2, %3;" : "=l"(d) : "l"(a), "l"(b), "l"(c))
#define PACK_F32X2(out, lo, hi) \
    asm("mov.b64 %0, {%1, %2};" : "=l"(out) : "r"(__float_as_uint(lo)), "r"(__float_as_uint(hi)))

__device__ __forceinline__ float f32x2_lo(u64 v) { return __uint_as_float((unsigned)(v & 0xFFFFFFFFu)); }
__device__ __forceinline__ float f32x2_hi(u64 v) { return __uint_as_float((unsigned)(v >> 32)); }
__device__ __forceinline__ float f32x2_sum(u64 v) { return f32x2_lo(v) + f32x2_hi(v); }

// Scratch
__device__ __align__(16) float g_partial[KDIM * NATOMS];        // force partials (3 MB)
__device__ __align__(16) float g_separt[(NSTR + 1) * NATOMS];   // stress + energy partials
__device__ __align__(16) float g_G[NATOMS * DDIM];              // per-atom dE/ddesc

// ---------------------------------------------------------------------------
// Kernel 1: species-batched MLP fwd+bwd. Each block self-assigns a
// (species, 4-atom tile) via warp-ballot scans of species[]. Full W0[s],
// W1[s] staged in smem. Thread (ty,tx): ty=tid>>2 -> 2 rows, tx=tid&3 -> atom.
// ---------------------------------------------------------------------------
__global__ __launch_bounds__(256) void nnp_mlp_kernel(
    const float* __restrict__ desc,   // [N, D]
    const float* __restrict__ SG,     // [N, 6, D]
    const float* __restrict__ W0,     // [S, H, D]
    const float* __restrict__ b0,     // [S, H]
    const float* __restrict__ W1,     // [S, H, H]
    const float* __restrict__ b1,     // [S, H]
    const float* __restrict__ W2,     // [S, 1, H]
    const float* __restrict__ b2,     // [S, 1]
    const int*   __restrict__ species)
{
    const int tid  = threadIdx.x;
    const int ty   = tid >> 2;     // 0..63 -> rows ty*2, ty*2+1
    const int tx   = tid & 3;      // atom within tile
    const int wid  = tid >> 5;
    const int lane = tid & 31;
    const int rbase = ty * 2;

    extern __shared__ float sm[];
    float* W0s = sm;                    // 16384 floats
    float* W1s = sm + 16384;            // 16384 floats
    float* X   = sm + 32768;            // TILE*XS (descriptors)
    float* H0  = X  + TILE * XS;        // h0, later G
    float* A0  = H0 + TILE * XS;        // 1-h0^2, later d0
    float* D1  = A0 + TILE * XS;
    float* Ep  = D1 + TILE * XS;        // 256 energy partials
    __shared__ int idx[TILE];
    __shared__ int sh_cnt[NSPEC];
    __shared__ int sh_s, sh_j, sh_m;

    // ---- pass 1: species counts (warp 0, ballot) ----
    if (wid == 0) {
        int c0 = 0, c1 = 0, c2 = 0, c3 = 0;
        for (int c = 0; c < NATOMS; c += 32) {
            const int spv = species[c + lane];
            c0 += __popc(__ballot_sync(0xFFFFFFFFu, spv == 0));
            c1 += __popc(__ballot_sync(0xFFFFFFFFu, spv == 1));
            c2 += __popc(__ballot_sync(0xFFFFFFFFu, spv == 2));
            c3 += __popc(__ballot_sync(0xFFFFFFFFu, spv == 3));
        }
        if (lane == 0) { sh_cnt[0] = c0; sh_cnt[1] = c1; sh_cnt[2] = c2; sh_cnt[3] = c3; }
    }
    __syncthreads();

    if (tid == 0) {
        int b = blockIdx.x, sp = 0, acc = 0;
        for (; sp < NSPEC; sp++) {
            const int t = (sh_cnt[sp] + TILE - 1) / TILE;
            if (b < acc + t) break;
            acc += t;
        }
        sh_s = sp;
        if (sp < NSPEC) {
            const int jj = b - acc;
            sh_j = jj;
            const int mm = sh_cnt[sp] - jj * TILE;
            sh_m = mm > TILE ? TILE : mm;
        }
    }
    __syncthreads();
    const int s = sh_s;
    if (s >= NSPEC) return;       // idle slack block
    const int j = sh_j;
    const int m = sh_m;

    // ---- pass 2: atom indices for this tile (warp 0, ballot rank) ----
    if (wid == 0) {
        int base = 0;
        for (int c = 0; c < NATOMS; c += 32) {
            const int spv = species[c + lane];
            const unsigned mask = __ballot_sync(0xFFFFFFFFu, spv == s);
            if (spv == s) {
                const int rank = base + __popc(mask & ((1u << lane) - 1u));
                const int rel = rank - j * TILE;
                if (rel >= 0 && rel < TILE) idx[rel] = c + lane;
            }
            base += __popc(mask);
        }
    }
    __syncthreads();

    // ---- stage descriptors + full W0/W1 ----
    for (int e = tid; e < TILE * DDIM; e += 256) {
        const int a = e >> 7, d = e & 127;
        X[a * XS + d] = (a < m) ? desc[(size_t)idx[a] * DDIM + d] : 0.f;
    }
    {
        const float4* w0g = (const float4*)(W0 + (size_t)s * DDIM * DDIM);
        const float4* w1g = (const float4*)(W1 + (size_t)s * DDIM * DDIM);
        float4* w0s = (float4*)W0s;
        float4* w1s = (float4*)W1s;
        for (int f = tid; f < 4096; f += 256) { w0s[f] = w0g[f]; w1s[f] = w1g[f]; }
    }
    __syncthreads();

    // ---- forward layer 0 ----
    {
        u64 acc0 = 0ull, acc1 = 0ull;
        const u64* Xd = (const u64*)(X + tx * XS);
        const u64* Wd = (const u64*)W0s;
        #pragma unroll 8
        for (int dq = 0; dq < 64; dq++) {
            const u64 xv = Xd[dq];
            FMA_F32X2(acc0, Wd[(size_t)(rbase + 0) * 64 + dq], xv, acc0);
            FMA_F32X2(acc1, Wd[(size_t)(rbase + 1) * 64 + dq], xv, acc1);
        }
        const float h0v = tanhf(f32x2_sum(acc0) + b0[s * DDIM + rbase + 0]);
        const float h1v = tanhf(f32x2_sum(acc1) + b0[s * DDIM + rbase + 1]);
        H0[tx * XS + rbase + 0] = h0v;  A0[tx * XS + rbase + 0] = 1.f - h0v * h0v;
        H0[tx * XS + rbase + 1] = h1v;  A0[tx * XS + rbase + 1] = 1.f - h1v * h1v;
    }
    __syncthreads();

    // ---- forward layer 1 + output partials ----
    {
        u64 acc0 = 0ull, acc1 = 0ull;
        const u64* Xd = (const u64*)(H0 + tx * XS);
        const u64* Wd = (const u64*)W1s;
        #pragma unroll 8
        for (int dq = 0; dq < 64; dq++) {
            const u64 xv = Xd[dq];
            FMA_F32X2(acc0, Wd[(size_t)(rbase + 0) * 64 + dq], xv, acc0);
            FMA_F32X2(acc1, Wd[(size_t)(rbase + 1) * 64 + dq], xv, acc1);
        }
        const float h0v = tanhf(f32x2_sum(acc0) + b1[s * DDIM + rbase + 0]);
        const float h1v = tanhf(f32x2_sum(acc1) + b1[s * DDIM + rbase + 1]);
        const float w2a = W2[s * DDIM + rbase + 0];
        const float w2b = W2[s * DDIM + rbase + 1];
        Ep[tid] = w2a * h0v + w2b * h1v;
        D1[tx * XS + rbase + 0] = w2a * (1.f - h0v * h0v);
        D1[tx * XS + rbase + 1] = w2b * (1.f - h1v * h1v);
    }
    __syncthreads();

    // ---- energy per atom ----
    if (tid < m) {
        float e = b2[s];
        #pragma unroll
        for (int t2 = 0; t2 < 64; t2++) e += Ep[t2 * 4 + tid];
        g_separt[NSTR * NATOMS + idx[tid]] = e;
    }

    // ---- backward: D0 = (W1^T @ D1) * A0 ----
    {
        u64 acca = 0ull, accb = 0ull;
        const float* d1p = D1 + tx * XS;
        #pragma unroll 4
        for (int jj = 0; jj < DDIM; jj += 2) {
            const float dva = d1p[jj], dvb = d1p[jj + 1];
            u64 da, db; PACK_F32X2(da, dva, dva); PACK_F32X2(db, dvb, dvb);
            FMA_F32X2(acca, *(const u64*)(W1s + (size_t)jj * DDIM + rbase), da, acca);
            FMA_F32X2(accb, *(const u64*)(W1s + (size_t)(jj + 1) * DDIM + rbase), db, accb);
        }
        A0[tx * XS + rbase + 0] *= f32x2_lo(acca) + f32x2_lo(accb);
        A0[tx * XS + rbase + 1] *= f32x2_hi(acca) + f32x2_hi(accb);
    }
    __syncthreads();

    // ---- backward: G = W0^T @ D0 -> H0 (reused) + g_G ----
    {
        u64 acca = 0ull, accb = 0ull;
        const float* d0p = A0 + tx * XS;
        #pragma unroll 4
        for (int jj = 0; jj < DDIM; jj += 2) {
            const float dva = d0p[jj], dvb = d0p[jj + 1];
            u64 da, db; PACK_F32X2(da, dva, dva); PACK_F32X2(db, dvb, dvb);
            FMA_F32X2(acca, *(const u64*)(W0s + (size_t)jj * DDIM + rbase), da, acca);
            FMA_F32X2(accb, *(const u64*)(W0s + (size_t)(jj + 1) * DDIM + rbase), db, accb);
        }
        const float g0 = f32x2_lo(acca) + f32x2_lo(accb);
        const float g1 = f32x2_hi(acca) + f32x2_hi(accb);
        H0[tx * XS + rbase + 0] = g0;
        H0[tx * XS + rbase + 1] = g1;
        if (tx < m)
            *(float2*)(g_G + (size_t)idx[tx] * DDIM + rbase) = make_float2(g0, g1);
    }
    __syncthreads();

    // ---- stress partials: warp per (atom, stress row) ----
    for (int t = wid; t < NSTR * m; t += 8) {
        const int a  = t / NSTR;
        const int rs = t % NSTR;
        const int n  = idx[a];
        const float4 v = ((const float4*)(SG + ((size_t)n * NSTR + rs) * DDIM))[lane];
        const float4 g = ((const float4*)(H0 + a * XS))[lane];
        float sv = v.x * g.x + v.y * g.y + v.z * g.z + v.w * g.w;
        #pragma unroll
        for (int off = 16; off > 0; off >>= 1)
            sv += __shfl_xor_sync(0xFFFFFFFFu, sv, off);
        if (lane == 0) g_separt[(size_t)rs * NATOMS + n] = sv;
    }
}

// ---------------------------------------------------------------------------
// Kernel 2: stream coord_grads (403 MB), atom-major — measured ~roofline.
// ---------------------------------------------------------------------------
__global__ __launch_bounds__(256) void nnp_stream_kernel(
    const float* __restrict__ CG)     // [N, KDIM, D]
{
    const int b    = blockIdx.x;
    const int n    = b / 6;
    const int chnk = b % 6;
    const int wid  = threadIdx.x >> 5;
    const int lane = threadIdx.x & 31;

    const float4 gv = reinterpret_cast<const float4*>(g_G + (size_t)n * DDIM)[lane];

    const int k0 = chnk * 256 + wid * 32;
    const float4* base = reinterpret_cast<const float4*>(
        CG + ((size_t)n * KDIM + k0) * DDIM);
    float* outp = g_partial + (size_t)k0 * NATOMS + n;

    #pragma unroll
    for (int it = 0; it < 8; it++) {
        const float4* p = base + (size_t)(it * 4) * 32 + lane;
        float4 v0 = __ldcs(p + 0 * 32);
        float4 v1 = __ldcs(p + 1 * 32);
        float4 v2 = __ldcs(p + 2 * 32);
        float4 v3 = __ldcs(p + 3 * 32);
        float s0 = v0.x * gv.x + v0.y * gv.y + v0.z * gv.z + v0.w * gv.w;
        float s1 = v1.x * gv.x + v1.y * gv.y + v1.z * gv.z + v1.w * gv.w;
        float s2 = v2.x * gv.x + v2.y * gv.y + v2.z * gv.z + v2.w * gv.w;
        float s3 = v3.x * gv.x + v3.y * gv.y + v3.z * gv.z + v3.w * gv.w;
        #pragma unroll
        for (int off = 16; off > 0; off >>= 1) {
            s0 += __shfl_xor_sync(0xFFFFFFFFu, s0, off);
            s1 += __shfl_xor_sync(0xFFFFFFFFu, s1, off);
            s2 += __shfl_xor_sync(0xFFFFFFFFu, s2, off);
            s3 += __shfl_xor_sync(0xFFFFFFFFu, s3, off);
        }
        if (lane == 0) {
            outp[(size_t)(it * 4 + 0) * NATOMS] = s0;
            outp[(size_t)(it * 4 + 1) * NATOMS] = s1;
            outp[(size_t)(it * 4 + 2) * NATOMS] = s2;
            outp[(size_t)(it * 4 + 3) * NATOMS] = s3;
        }
    }
}

// ---------------------------------------------------------------------------
// Kernel 3: deterministic reduce. Warp per output slot over 512 atoms.
// ---------------------------------------------------------------------------
__global__ void nnp_reduce_kernel(float* __restrict__ out,
                                  const float* __restrict__ volume)
{
    const int k    = blockIdx.x * 8 + (threadIdx.x >> 5);
    const int lane = threadIdx.x & 31;
    if (k >= KTOT) return;

    const float* src = (k < KDIM) ? (g_partial + (size_t)k * NATOMS)
                                  : (g_separt + (size_t)(k - KDIM) * NATOMS);
    const float4* base = reinterpret_cast<const float4*>(src);
    float4 v0 = base[lane + 0 * 32];
    float4 v1 = base[lane + 1 * 32];
    float4 v2 = base[lane + 2 * 32];
    float4 v3 = base[lane + 3 * 32];
    float s = (v0.x + v0.y + v0.z + v0.w) + (v1.x + v1.y + v1.z + v1.w)
            + (v2.x + v2.y + v2.z + v2.w) + (v3.x + v3.y + v3.z + v3.w);
    #pragma unroll
    for (int off = 16; off > 0; off >>= 1)
        s += __shfl_xor_sync(0xFFFFFFFFu, s, off);

    if (lane == 0) {
        if (k < KDIM)             out[1 + k] = s;
        else if (k < KDIM + NSTR) out[1 + KDIM + (k - KDIM)] = -s / volume[0];
        else                      out[0] = s;
    }
}

extern "C" void kernel_launch(void* const* d_in, const int* in_sizes, int n_in,
                              void* d_out, int out_size)
{
    const float* desc    = (const float*)d_in[0];
    const float* CG      = (const float*)d_in[1];
    const float* SG      = (const float*)d_in[2];
    const float* W0      = (const float*)d_in[3];
    const float* b0      = (const float*)d_in[4];
    const float* W1      = (const float*)d_in[5];
    const float* b1      = (const float*)d_in[6];
    const float* W2      = (const float*)d_in[7];
    const float* b2      = (const float*)d_in[8];
    const float* volume  = (const float*)d_in[9];
    const int*   species = (const int*)  d_in[10];
    float* out = (float*)d_out;

    const int mlp_smem = (32768 + 4 * TILE * XS + 256) * sizeof(float);  // ~140.5 KB
    cudaFuncSetAttribute(nnp_mlp_kernel,
                         cudaFuncAttributeMaxDynamicSharedMemorySize, mlp_smem);

    nnp_mlp_kernel<<<NTILES_MAX, 256, mlp_smem>>>(desc, SG, W0, b0, W1, b1, W2, b2, species);
    nnp_stream_kernel<<<NATOMS * 6, 256>>>(CG);
    nnp_reduce_kernel<<<(KTOT + 7) / 8, 256>>>(out, volume);
}

// round 7
// speedup vs baseline: 1.8985x; 1.0196x over previous
#include <cuda_runtime.h>
#include <cstddef>

#define NATOMS 512
#define DDIM   128
#define KDIM   1536   // 3*N
#define NSTR   6
#define KTOT   (KDIM + NSTR + 1)
#define NSPEC  4
#define TILE   4      // atoms per MLP block
#define XS     132    // activation smem row stride (floats)
#define WS     130    // weight smem row stride (floats) — conflict-free padding
#define WS64   65     // same, in u64 units
#define NTILES_MAX (NATOMS / TILE + NSPEC - 1)   // 131

typedef unsigned long long u64;

// fma.rn.f32x2: packed 2xf32 FMA (sm_100+), not emitted by ptxas from C++.
#define FMA_F32X2(d, a, b, c) \
    asm("fma.rn.f32x2 %0, %1, %2, %3;" : "=l"(d) : "l"(a), "l"(b), "l"(c))
#define PACK_F32X2(out, lo, hi) \
    asm("mov.b64 %0, {%1, %2};" : "=l"(out) : "r"(__float_as_uint(lo)), "r"(__float_as_uint(hi)))

__device__ __forceinline__ float f32x2_lo(u64 v) { return __uint_as_float((unsigned)(v & 0xFFFFFFFFu)); }
__device__ __forceinline__ float f32x2_hi(u64 v) { return __uint_as_float((unsigned)(v >> 32)); }
__device__ __forceinline__ float f32x2_sum(u64 v) { return f32x2_lo(v) + f32x2_hi(v); }

// Scratch
__device__ __align__(16) float g_partial[KDIM * NATOMS];        // force partials (3 MB)
__device__ __align__(16) float g_separt[(NSTR + 1) * NATOMS];   // stress + energy partials
__device__ __align__(16) float g_G[NATOMS * DDIM];              // per-atom dE/ddesc

// ---------------------------------------------------------------------------
// Kernel 1: species-batched MLP fwd+bwd. Block self-assigns a
// (species, 4-atom tile) via warp-ballot scans. W0[s], W1[s] staged in smem
// with 130-float row pitch (bank-conflict-free for row AND column access).
// Thread (ty,tx): ty=tid>>2 -> rows ty*2,ty*2+1; tx=tid&3 -> atom.
// ---------------------------------------------------------------------------
__global__ __launch_bounds__(256) void nnp_mlp_kernel(
    const float* __restrict__ desc,   // [N, D]
    const float* __restrict__ SG,     // [N, 6, D]
    const float* __restrict__ W0,     // [S, H, D]
    const float* __restrict__ b0,     // [S, H]
    const float* __restrict__ W1,     // [S, H, H]
    const float* __restrict__ b1,     // [S, H]
    const float* __restrict__ W2,     // [S, 1, H]
    const float* __restrict__ b2,     // [S, 1]
    const int*   __restrict__ species)
{
    const int tid  = threadIdx.x;
    const int ty   = tid >> 2;     // 0..63 -> rows ty*2, ty*2+1
    const int tx   = tid & 3;      // atom within tile
    const int wid  = tid >> 5;
    const int lane = tid & 31;
    const int rbase = ty * 2;

    extern __shared__ float sm[];
    float* W0s = sm;                      // 128*130 floats
    float* W1s = sm + DDIM * WS;          // 128*130 floats
    float* X   = sm + 2 * DDIM * WS;      // TILE*XS (descriptors)
    float* H0  = X  + TILE * XS;          // h0, later G
    float* A0  = H0 + TILE * XS;          // 1-h0^2, later d0
    float* D1  = A0 + TILE * XS;
    float* Ep  = D1 + TILE * XS;          // 256 energy partials
    __shared__ int idx[TILE];
    __shared__ int sh_cnt[NSPEC];
    __shared__ int sh_s, sh_j, sh_m;

    // ---- pass 1: species counts (warp 0, ballot) ----
    if (wid == 0) {
        int c0 = 0, c1 = 0, c2 = 0, c3 = 0;
        for (int c = 0; c < NATOMS; c += 32) {
            const int spv = species[c + lane];
            c0 += __popc(__ballot_sync(0xFFFFFFFFu, spv == 0));
            c1 += __popc(__ballot_sync(0xFFFFFFFFu, spv == 1));
            c2 += __popc(__ballot_sync(0xFFFFFFFFu, spv == 2));
            c3 += __popc(__ballot_sync(0xFFFFFFFFu, spv == 3));
        }
        if (lane == 0) { sh_cnt[0] = c0; sh_cnt[1] = c1; sh_cnt[2] = c2; sh_cnt[3] = c3; }
    }
    __syncthreads();

    if (tid == 0) {
        int b = blockIdx.x, sp = 0, acc = 0;
        for (; sp < NSPEC; sp++) {
            const int t = (sh_cnt[sp] + TILE - 1) / TILE;
            if (b < acc + t) break;
            acc += t;
        }
        sh_s = sp;
        if (sp < NSPEC) {
            const int jj = b - acc;
            sh_j = jj;
            const int mm = sh_cnt[sp] - jj * TILE;
            sh_m = mm > TILE ? TILE : mm;
        }
    }
    __syncthreads();
    const int s = sh_s;
    if (s >= NSPEC) return;       // idle slack block
    const int j = sh_j;
    const int m = sh_m;

    // ---- pass 2: atom indices for this tile (warp 0, ballot rank) ----
    if (wid == 0) {
        int base = 0;
        for (int c = 0; c < NATOMS; c += 32) {
            const int spv = species[c + lane];
            const unsigned mask = __ballot_sync(0xFFFFFFFFu, spv == s);
            if (spv == s) {
                const int rank = base + __popc(mask & ((1u << lane) - 1u));
                const int rel = rank - j * TILE;
                if (rel >= 0 && rel < TILE) idx[rel] = c + lane;
            }
            base += __popc(mask);
        }
    }
    __syncthreads();

    // ---- stage descriptors + W0/W1 (padded pitch, float2 copies) ----
    for (int e = tid; e < TILE * DDIM; e += 256) {
        const int a = e >> 7, d = e & 127;
        X[a * XS + d] = (a < m) ? desc[(size_t)idx[a] * DDIM + d] : 0.f;
    }
    {
        const float2* w0g = (const float2*)(W0 + (size_t)s * DDIM * DDIM);
        const float2* w1g = (const float2*)(W1 + (size_t)s * DDIM * DDIM);
        #pragma unroll 8
        for (int f = tid; f < DDIM * 64; f += 256) {
            const int r = f >> 6, d2 = f & 63;
            *(float2*)(W0s + r * WS + d2 * 2) = w0g[f];
            *(float2*)(W1s + r * WS + d2 * 2) = w1g[f];
        }
    }
    __syncthreads();

    // ---- forward layer 0 ----
    {
        u64 acc0 = 0ull, acc1 = 0ull;
        const u64* Xd = (const u64*)(X + tx * XS);
        const u64* Wd = (const u64*)W0s;
        #pragma unroll 8
        for (int dq = 0; dq < 64; dq++) {
            const u64 xv = Xd[dq];
            FMA_F32X2(acc0, Wd[(size_t)(rbase + 0) * WS64 + dq], xv, acc0);
            FMA_F32X2(acc1, Wd[(size_t)(rbase + 1) * WS64 + dq], xv, acc1);
        }
        const float h0v = tanhf(f32x2_sum(acc0) + b0[s * DDIM + rbase + 0]);
        const float h1v = tanhf(f32x2_sum(acc1) + b0[s * DDIM + rbase + 1]);
        H0[tx * XS + rbase + 0] = h0v;  A0[tx * XS + rbase + 0] = 1.f - h0v * h0v;
        H0[tx * XS + rbase + 1] = h1v;  A0[tx * XS + rbase + 1] = 1.f - h1v * h1v;
    }
    __syncthreads();

    // ---- forward layer 1 + output partials ----
    {
        u64 acc0 = 0ull, acc1 = 0ull;
        const u64* Xd = (const u64*)(H0 + tx * XS);
        const u64* Wd = (const u64*)W1s;
        #pragma unroll 8
        for (int dq = 0; dq < 64; dq++) {
            const u64 xv = Xd[dq];
            FMA_F32X2(acc0, Wd[(size_t)(rbase + 0) * WS64 + dq], xv, acc0);
            FMA_F32X2(acc1, Wd[(size_t)(rbase + 1) * WS64 + dq], xv, acc1);
        }
        const float h0v = tanhf(f32x2_sum(acc0) + b1[s * DDIM + rbase + 0]);
        const float h1v = tanhf(f32x2_sum(acc1) + b1[s * DDIM + rbase + 1]);
        const float w2a = W2[s * DDIM + rbase + 0];
        const float w2b = W2[s * DDIM + rbase + 1];
        Ep[tid] = w2a * h0v + w2b * h1v;
        D1[tx * XS + rbase + 0] = w2a * (1.f - h0v * h0v);
        D1[tx * XS + rbase + 1] = w2b * (1.f - h1v * h1v);
    }
    __syncthreads();

    // ---- energy per atom ----
    if (tid < m) {
        float e = b2[s];
        #pragma unroll
        for (int t2 = 0; t2 < 64; t2++) e += Ep[t2 * 4 + tid];
        g_separt[NSTR * NATOMS + idx[tid]] = e;
    }

    // ---- backward: D0 = (W1^T @ D1) * A0 ----
    {
        u64 acca = 0ull, accb = 0ull;
        const float* d1p = D1 + tx * XS;
        #pragma unroll 4
        for (int jj = 0; jj < DDIM; jj += 2) {
            const float dva = d1p[jj], dvb = d1p[jj + 1];
            u64 da, db; PACK_F32X2(da, dva, dva); PACK_F32X2(db, dvb, dvb);
            FMA_F32X2(acca, *(const u64*)(W1s + (size_t)jj * WS + rbase), da, acca);
            FMA_F32X2(accb, *(const u64*)(W1s + (size_t)(jj + 1) * WS + rbase), db, accb);
        }
        A0[tx * XS + rbase + 0] *= f32x2_lo(acca) + f32x2_lo(accb);
        A0[tx * XS + rbase + 1] *= f32x2_hi(acca) + f32x2_hi(accb);
    }
    __syncthreads();

    // ---- backward: G = W0^T @ D0 -> H0 (reused) + g_G ----
    {
        u64 acca = 0ull, accb = 0ull;
        const float* d0p = A0 + tx * XS;
        #pragma unroll 4
        for (int jj = 0; jj < DDIM; jj += 2) {
            const float dva = d0p[jj], dvb = d0p[jj + 1];
            u64 da, db; PACK_F32X2(da, dva, dva); PACK_F32X2(db, dvb, dvb);
            FMA_F32X2(acca, *(const u64*)(W0s + (size_t)jj * WS + rbase), da, acca);
            FMA_F32X2(accb, *(const u64*)(W0s + (size_t)(jj + 1) * WS + rbase), db, accb);
        }
        const float g0 = f32x2_lo(acca) + f32x2_lo(accb);
        const float g1 = f32x2_hi(acca) + f32x2_hi(accb);
        H0[tx * XS + rbase + 0] = g0;
        H0[tx * XS + rbase + 1] = g1;
        if (tx < m)
            *(float2*)(g_G + (size_t)idx[tx] * DDIM + rbase) = make_float2(g0, g1);
    }
    __syncthreads();

    // ---- stress partials: warp per (atom, stress row) ----
    for (int t = wid; t < NSTR * m; t += 8) {
        const int a  = t / NSTR;
        const int rs = t % NSTR;
        const int n  = idx[a];
        const float4 v = ((const float4*)(SG + ((size_t)n * NSTR + rs) * DDIM))[lane];
        const float4 g = ((const float4*)(H0 + a * XS))[lane];
        float sv = v.x * g.x + v.y * g.y + v.z * g.z + v.w * g.w;
        #pragma unroll
        for (int off = 16; off > 0; off >>= 1)
            sv += __shfl_xor_sync(0xFFFFFFFFu, sv, off);
        if (lane == 0) g_separt[(size_t)rs * NATOMS + n] = sv;
    }
}

// ---------------------------------------------------------------------------
// Kernel 2: stream coord_grads (403 MB), atom-major — measured ~roofline.
// ---------------------------------------------------------------------------
__global__ __launch_bounds__(256) void nnp_stream_kernel(
    const float* __restrict__ CG)     // [N, KDIM, D]
{
    const int b    = blockIdx.x;
    const int n    = b / 6;
    const int chnk = b % 6;
    const int wid  = threadIdx.x >> 5;
    const int lane = threadIdx.x & 31;

    const float4 gv = reinterpret_cast<const float4*>(g_G + (size_t)n * DDIM)[lane];

    const int k0 = chnk * 256 + wid * 32;
    const float4* base = reinterpret_cast<const float4*>(
        CG + ((size_t)n * KDIM + k0) * DDIM);
    float* outp = g_partial + (size_t)k0 * NATOMS + n;

    #pragma unroll
    for (int it = 0; it < 8; it++) {
        const float4* p = base + (size_t)(it * 4) * 32 + lane;
        float4 v0 = __ldcs(p + 0 * 32);
        float4 v1 = __ldcs(p + 1 * 32);
        float4 v2 = __ldcs(p + 2 * 32);
        float4 v3 = __ldcs(p + 3 * 32);
        float s0 = v0.x * gv.x + v0.y * gv.y + v0.z * gv.z + v0.w * gv.w;
        float s1 = v1.x * gv.x + v1.y * gv.y + v1.z * gv.z + v1.w * gv.w;
        float s2 = v2.x * gv.x + v2.y * gv.y + v2.z * gv.z + v2.w * gv.w;
        float s3 = v3.x * gv.x + v3.y * gv.y + v3.z * gv.z + v3.w * gv.w;
        #pragma unroll
        for (int off = 16; off > 0; off >>= 1) {
            s0 += __shfl_xor_sync(0xFFFFFFFFu, s0, off);
            s1 += __shfl_xor_sync(0xFFFFFFFFu, s1, off);
            s2 += __shfl_xor_sync(0xFFFFFFFFu, s2, off);
            s3 += __shfl_xor_sync(0xFFFFFFFFu, s3, off);
        }
        if (lane == 0) {
            outp[(size_t)(it * 4 + 0) * NATOMS] = s0;
            outp[(size_t)(it * 4 + 1) * NATOMS] = s1;
            outp[(size_t)(it * 4 + 2) * NATOMS] = s2;
            outp[(size_t)(it * 4 + 3) * NATOMS] = s3;
        }
    }
}

// ---------------------------------------------------------------------------
// Kernel 3: deterministic reduce. Warp per output slot over 512 atoms.
// ---------------------------------------------------------------------------
__global__ void nnp_reduce_kernel(float* __restrict__ out,
                                  const float* __restrict__ volume)
{
    const int k    = blockIdx.x * 8 + (threadIdx.x >> 5);
    const int lane = threadIdx.x & 31;
    if (k >= KTOT) return;

    const float* src = (k < KDIM) ? (g_partial + (size_t)k * NATOMS)
                                  : (g_separt + (size_t)(k - KDIM) * NATOMS);
    const float4* base = reinterpret_cast<const float4*>(src);
    float4 v0 = base[lane + 0 * 32];
    float4 v1 = base[lane + 1 * 32];
    float4 v2 = base[lane + 2 * 32];
    float4 v3 = base[lane + 3 * 32];
    float s = (v0.x + v0.y + v0.z + v0.w) + (v1.x + v1.y + v1.z + v1.w)
            + (v2.x + v2.y + v2.z + v2.w) + (v3.x + v3.y + v3.z + v3.w);
    #pragma unroll
    for (int off = 16; off > 0; off >>= 1)
        s += __shfl_xor_sync(0xFFFFFFFFu, s, off);

    if (lane == 0) {
        if (k < KDIM)             out[1 + k] = s;
        else if (k < KDIM + NSTR) out[1 + KDIM + (k - KDIM)] = -s / volume[0];
        else                      out[0] = s;
    }
}

extern "C" void kernel_launch(void* const* d_in, const int* in_sizes, int n_in,
                              void* d_out, int out_size)
{
    const float* desc    = (const float*)d_in[0];
    const float* CG      = (const float*)d_in[1];
    const float* SG      = (const float*)d_in[2];
    const float* W0      = (const float*)d_in[3];
    const float* b0      = (const float*)d_in[4];
    const float* W1      = (const float*)d_in[5];
    const float* b1      = (const float*)d_in[6];
    const float* W2      = (const float*)d_in[7];
    const float* b2      = (const float*)d_in[8];
    const float* volume  = (const float*)d_in[9];
    const int*   species = (const int*)  d_in[10];
    float* out = (float*)d_out;

    const int mlp_smem = (2 * DDIM * WS + 4 * TILE * XS + 256) * sizeof(float); // ~142 KB
    cudaFuncSetAttribute(nnp_mlp_kernel,
                         cudaFuncAttributeMaxDynamicSharedMemorySize, mlp_smem);

    nnp_mlp_kernel<<<NTILES_MAX, 256, mlp_smem>>>(desc, SG, W0, b0, W1, b1, W2, b2, species);
    nnp_stream_kernel<<<NATOMS * 6, 256>>>(CG);
    nnp_reduce_kernel<<<(KTOT + 7) / 8, 256>>>(out, volume);
}